// round 5
// baseline (speedup 1.0000x reference)
#include <cuda_runtime.h>
#include <cstdint>
#include <math.h>

// Trilinear scatter of B x N points into B x 64^3 grids.
// One 8-CTA cluster per batch; the 1MB grid lives in distributed shared
// memory (8 x 128KB slabs). Atomic adds are routed to the owning CTA via
// mapa + red.shared::cluster, removing all fp32 atomics from the L2 ALU.
#define HALF   32
#define GSIDE  64
#define GRID3  (GSIDE * GSIDE * GSIDE)
#define CLUSTER 8
#define SLAB_X  (GSIDE / CLUSTER)                 // 8 x-planes per CTA
#define SLAB_FLOATS (SLAB_X * GSIDE * GSIDE)     // 32768 floats = 128KB
#define THREADS 512

__device__ __forceinline__ uint32_t smem_u32(const void* p) {
    uint32_t a;
    asm("{ .reg .u64 t; cvta.to.shared.u64 t, %1; cvt.u32.u64 %0, t; }"
        : "=r"(a) : "l"(p));
    return a;
}
__device__ __forceinline__ uint32_t mapa_u32(uint32_t a, uint32_t r) {
    uint32_t o;
    asm("mapa.shared::cluster.u32 %0, %1, %2;" : "=r"(o) : "r"(a), "r"(r));
    return o;
}
// Fire-and-forget fp32 add into (possibly remote) cluster shared memory.
__device__ __forceinline__ void redc(uint32_t a, float v) {
    asm volatile("red.shared::cluster.add.f32 [%0], %1;"
                 :: "r"(a), "f"(v) : "memory");
}

__global__ void __launch_bounds__(THREADS, 1)
gridding_cluster_kernel(const float* __restrict__ pt,
                        float* __restrict__ out,
                        int N) {
    extern __shared__ float slab[];   // 32768 floats: x-slab [8*rank, 8*rank+8)
    int tid = threadIdx.x;
    uint32_t rank;
    asm("mov.u32 %0, %%cluster_ctarank;" : "=r"(rank));
    int b = blockIdx.y;

    // Zero my slab.
    float4* s4 = (float4*)slab;
    #pragma unroll 4
    for (int i = tid; i < SLAB_FLOATS / 4; i += THREADS)
        s4[i] = make_float4(0.f, 0.f, 0.f, 0.f);

    // All slabs zeroed before anyone scatters.
    asm volatile("barrier.cluster.arrive.aligned;" ::: "memory");
    asm volatile("barrier.cluster.wait.aligned;" ::: "memory");

    uint32_t sbase = smem_u32(slab);
    const float* bp = pt + (size_t)b * N * 3;

    // Interleaved point partition across the 8 CTAs of the cluster.
    int ct = (int)rank * THREADS + tid;
    for (int n = ct; n < N; n += CLUSTER * THREADS) {
        float x = bp[3 * n + 0] * (float)HALF;
        float y = bp[3 * n + 1] * (float)HALF;
        float z = bp[3 * n + 2] * (float)HALF;

        // reference drops points whose scaled coord-sum is exactly 0
        float m = ((x + y + z) != 0.0f) ? 1.0f : 0.0f;

        float fx = floorf(x), fy = floorf(y), fz = floorf(z);
        float tx = x - fx, ty = y - fy, tz = z - fz;

        int ix = min(max((int)fx + HALF, 0), GSIDE - 2);
        int iy = min(max((int)fy + HALF, 0), GSIDE - 2);
        int iz = min(max((int)fz + HALF, 0), GSIDE - 2);
        int ix1 = ix + 1;

        float wx0 = 1.0f - tx, wx1 = tx;
        float wy0 = 1.0f - ty, wy1 = ty;
        float wz0 = (1.0f - tz) * m, wz1 = tz * m;

        float w00 = wx0 * wy0, w01 = wx0 * wy1;
        float w10 = wx1 * wy0, w11 = wx1 * wy1;

        // Owner rank from the x coordinate; address inside owner's slab.
        uint32_t off0 = (((uint32_t)(ix  & (SLAB_X - 1)) * GSIDE + (uint32_t)iy) * GSIDE + (uint32_t)iz) * 4u;
        uint32_t off1 = (((uint32_t)(ix1 & (SLAB_X - 1)) * GSIDE + (uint32_t)iy) * GSIDE + (uint32_t)iz) * 4u;
        uint32_t a0 = mapa_u32(sbase, (uint32_t)(ix  >> 3)) + off0;
        uint32_t a1 = mapa_u32(sbase, (uint32_t)(ix1 >> 3)) + off1;

        redc(a0,                 w00 * wz0);
        redc(a0 + 4,             w00 * wz1);
        redc(a0 + 4 * GSIDE,     w01 * wz0);
        redc(a0 + 4 * GSIDE + 4, w01 * wz1);
        redc(a1,                 w10 * wz0);
        redc(a1 + 4,             w10 * wz1);
        redc(a1 + 4 * GSIDE,     w11 * wz0);
        redc(a1 + 4 * GSIDE + 4, w11 * wz1);
    }

    // Make all outstanding remote reductions visible, then sync the cluster.
    asm volatile("fence.acq_rel.cluster;" ::: "memory");
    asm volatile("barrier.cluster.arrive.aligned;" ::: "memory");
    asm volatile("barrier.cluster.wait.aligned;" ::: "memory");

    // Each CTA owns its slab exclusively now: plain coalesced stores cover
    // the whole output, so no global memset is needed.
    float4* dst = (float4*)(out + (size_t)b * GRID3 + (size_t)rank * SLAB_FLOATS);
    #pragma unroll 4
    for (int i = tid; i < SLAB_FLOATS / 4; i += THREADS)
        dst[i] = s4[i];
}

extern "C" void kernel_launch(void* const* d_in, const int* in_sizes, int n_in,
                              void* d_out, int out_size) {
    const float* pt  = (const float*)d_in[0];
    float*       out = (float*)d_out;

    int B = out_size / GRID3;
    if (B < 1) B = 1;
    int N = (in_sizes[0] / 3) / B;

    cudaFuncSetAttribute(gridding_cluster_kernel,
                         cudaFuncAttributeMaxDynamicSharedMemorySize,
                         SLAB_FLOATS * sizeof(float));

    cudaLaunchConfig_t cfg = {};
    cfg.gridDim  = dim3(CLUSTER, B, 1);
    cfg.blockDim = dim3(THREADS, 1, 1);
    cfg.dynamicSmemBytes = SLAB_FLOATS * sizeof(float);

    cudaLaunchAttribute attrs[1];
    attrs[0].id = cudaLaunchAttributeClusterDimension;
    attrs[0].val.clusterDim.x = CLUSTER;
    attrs[0].val.clusterDim.y = 1;
    attrs[0].val.clusterDim.z = 1;
    cfg.attrs = attrs;
    cfg.numAttrs = 1;

    cudaLaunchKernelEx(&cfg, gridding_cluster_kernel, pt, out, N);
}

// round 8
// speedup vs baseline: 11.1374x; 11.1374x over previous
#include <cuda_runtime.h>
#include <cuda_fp16.h>
#include <cstdint>
#include <math.h>

// Trilinear scatter of B x N points into B x 64^3 grids.
// Strategy: the z-corner pair (iz, iz+1) is contiguous, so each of the 4
// (x,y) corners is one packed red.global.add.noftz.f16x2 -> 4 atomic words
// per point instead of 8 (LTS atomic ALU charges per 32-bit word).
// Parity grids keep the pair 4B-aligned for any iz; 2 replicas per parity
// shorten f16 accumulation chains for precision. Merge sums in fp32.
#define HALF_EXT 32
#define GSIDE    64
#define GRID3    (GSIDE * GSIDE * GSIDE)
#define CAP_B    32

// [replica(2) x parity(2)] f16 grids. parity 0 ("even"): voxel z at slot z.
// parity 1 ("odd"): voxel z at slot z+1 (so odd-iz pairs start on even slots).
// Layout index: rep*2 + par. Total 4 * 32 * 64^3 * 2B = 64 MiB.
__device__ __half g_scratch[4][(size_t)CAP_B * GRID3];

__device__ __forceinline__ void red_h2(__half* p, float lo, float hi) {
    __half2 v = __floats2half2_rn(lo, hi);
    asm volatile("red.global.add.noftz.f16x2 [%0], %1;"
                 :: "l"(p), "r"(*(const unsigned int*)&v) : "memory");
}
__device__ __forceinline__ void red_f32(float* a, float v) {
    asm volatile("red.global.add.f32 [%0], %1;" :: "l"(a), "f"(v) : "memory");
}

__global__ void scatter_h2_kernel(const float* __restrict__ pt, int N) {
    int n = blockIdx.x * blockDim.x + threadIdx.x;
    int b = blockIdx.y;
    if (n >= N) return;

    const float* p = pt + ((size_t)b * N + n) * 3;
    float x = p[0] * (float)HALF_EXT;
    float y = p[1] * (float)HALF_EXT;
    float z = p[2] * (float)HALF_EXT;

    // reference drops points whose scaled coord-sum is exactly 0
    float m = ((x + y + z) != 0.0f) ? 1.0f : 0.0f;

    float fx = floorf(x), fy = floorf(y), fz = floorf(z);
    float tx = x - fx, ty = y - fy, tz = z - fz;

    int ix = min(max((int)fx + HALF_EXT, 0), GSIDE - 2);
    int iy = min(max((int)fy + HALF_EXT, 0), GSIDE - 2);
    int iz = min(max((int)fz + HALF_EXT, 0), GSIDE - 2);

    float wx0 = 1.0f - tx, wx1 = tx;
    float wy0 = 1.0f - ty, wy1 = ty;
    float wz0 = (1.0f - tz) * m, wz1 = tz * m;

    int par  = iz & 1;
    int slot = iz + par;                 // even: pair lands 4B-aligned
    int rep  = threadIdx.x & 1;          // replica split for precision

    __half* base = g_scratch[rep * 2 + par] + (size_t)b * GRID3;
    __half* a00  = base + ((ix * GSIDE) + iy) * GSIDE + slot;

    red_h2(a00,                         wx0 * wy0 * wz0, wx0 * wy0 * wz1);
    red_h2(a00 + GSIDE,                 wx0 * wy1 * wz0, wx0 * wy1 * wz1);
    red_h2(a00 + GSIDE * GSIDE,         wx1 * wy0 * wz0, wx1 * wy0 * wz1);
    red_h2(a00 + GSIDE * GSIDE + GSIDE, wx1 * wy1 * wz0, wx1 * wy1 * wz1);
}

__global__ void merge_kernel(float* __restrict__ out, int total) {
    int i = blockIdx.x * blockDim.x + threadIdx.x;
    if (i >= total) return;
    int z = i & (GSIDE - 1);
    float s = __half2float(g_scratch[0][i]) + __half2float(g_scratch[2][i]);
    if (z < GSIDE - 1)   // odd-parity grid holds voxel z at slot z+1
        s += __half2float(g_scratch[1][i + 1]) + __half2float(g_scratch[3][i + 1]);
    out[i] = s;
}

// ---- fp32 fallback (round-1 design) for unexpected shapes ----
__global__ void scatter_f32_kernel(const float* __restrict__ pt,
                                   float* __restrict__ out, int N) {
    int n = blockIdx.x * blockDim.x + threadIdx.x;
    int b = blockIdx.y;
    if (n >= N) return;
    const float* p = pt + ((size_t)b * N + n) * 3;
    float x = p[0] * 32.f, y = p[1] * 32.f, z = p[2] * 32.f;
    float m = ((x + y + z) != 0.0f) ? 1.0f : 0.0f;
    float fx = floorf(x), fy = floorf(y), fz = floorf(z);
    float tx = x - fx, ty = y - fy, tz = z - fz;
    int ix = min(max((int)fx + 32, 0), 62);
    int iy = min(max((int)fy + 32, 0), 62);
    int iz = min(max((int)fz + 32, 0), 62);
    float wx0 = 1.f - tx, wy0 = 1.f - ty;
    float wz0 = (1.f - tz) * m, wz1 = tz * m;
    float* g = out + (size_t)b * GRID3;
    float* r = g + (((size_t)ix * GSIDE + iy) * GSIDE + iz);
    red_f32(r,                       wx0 * wy0 * wz0);
    red_f32(r + 1,                   wx0 * wy0 * wz1);
    red_f32(r + GSIDE,               wx0 * ty  * wz0);
    red_f32(r + GSIDE + 1,           wx0 * ty  * wz1);
    red_f32(r + GSIDE * GSIDE,             tx * wy0 * wz0);
    red_f32(r + GSIDE * GSIDE + 1,         tx * wy0 * wz1);
    red_f32(r + GSIDE * GSIDE + GSIDE,     tx * ty  * wz0);
    red_f32(r + GSIDE * GSIDE + GSIDE + 1, tx * ty  * wz1);
}

extern "C" void kernel_launch(void* const* d_in, const int* in_sizes, int n_in,
                              void* d_out, int out_size) {
    const float* pt  = (const float*)d_in[0];
    float*       out = (float*)d_out;

    int B = out_size / GRID3;
    if (B < 1) B = 1;
    int N = (in_sizes[0] / 3) / B;

    if (B <= CAP_B) {
        void* sp = nullptr;
        cudaGetSymbolAddress(&sp, g_scratch);
        cudaMemsetAsync(sp, 0, sizeof(g_scratch));

        dim3 block(256, 1, 1);
        dim3 grid((N + 255) / 256, B, 1);
        scatter_h2_kernel<<<grid, block>>>(pt, N);

        int total = B * GRID3;
        merge_kernel<<<(total + 255) / 256, 256>>>(out, total);
    } else {
        cudaMemsetAsync(d_out, 0, (size_t)out_size * sizeof(float));
        dim3 block(256, 1, 1);
        dim3 grid((N + 255) / 256, B, 1);
        scatter_f32_kernel<<<grid, block>>>(pt, out, N);
    }
}

// round 12
// speedup vs baseline: 11.8537x; 1.0643x over previous
#include <cuda_runtime.h>
#include <cuda_fp16.h>
#include <cstdint>
#include <math.h>

// Trilinear scatter of B x N points into B x 64^3 grids.
// All 8 corners of each point are packed into ONE red.global.add.noftz.v4.f16x2
// (16 bytes, 8 f16) using an octant layout: 8 parity grids (px,py,pz), each
// storing voxel c at slot c+p per axis, laid out [xq][yq][zq][xl yl zl] so a
// point's 2x2x2 corner cube is one aligned 8-half block. One RED lane/point.
#define HALF_EXT 32
#define GSIDE    64
#define GRID3    (GSIDE * GSIDE * GSIDE)     // 262144 == 1<<18
#define CAP_B    32

// 8 parity grids x 32 batches x 64^3 f16 = 134 MB scratch.
__device__ __align__(16) __half g_oct[8][(size_t)CAP_B * GRID3];

__device__ __forceinline__ unsigned pack2(float lo, float hi) {
    __half2 v = __floats2half2_rn(lo, hi);
    return *(const unsigned*)&v;
}
__device__ __forceinline__ void red_v4h2(__half* p, unsigned a, unsigned b,
                                         unsigned c, unsigned d) {
    asm volatile("red.global.add.noftz.v4.f16x2 [%0], {%1,%2,%3,%4};"
                 :: "l"(p), "r"(a), "r"(b), "r"(c), "r"(d) : "memory");
}
__device__ __forceinline__ void red_f32(float* a, float v) {
    asm volatile("red.global.add.f32 [%0], %1;" :: "l"(a), "f"(v) : "memory");
}

__global__ void scatter_oct_kernel(const float* __restrict__ pt, int N) {
    int n = blockIdx.x * blockDim.x + threadIdx.x;
    int b = blockIdx.y;
    if (n >= N) return;

    const float* p = pt + ((size_t)b * N + n) * 3;
    float x = p[0] * (float)HALF_EXT;
    float y = p[1] * (float)HALF_EXT;
    float z = p[2] * (float)HALF_EXT;

    // reference drops points whose scaled coord-sum is exactly 0
    float m = ((x + y + z) != 0.0f) ? 1.0f : 0.0f;

    float fx = floorf(x), fy = floorf(y), fz = floorf(z);
    float tx = x - fx, ty = y - fy, tz = z - fz;

    int ix = min(max((int)fx + HALF_EXT, 0), GSIDE - 2);
    int iy = min(max((int)fy + HALF_EXT, 0), GSIDE - 2);
    int iz = min(max((int)fz + HALF_EXT, 0), GSIDE - 2);

    float wx0 = 1.0f - tx, wx1 = tx;
    float wy0 = 1.0f - ty, wy1 = ty;
    float wz0 = (1.0f - tz) * m, wz1 = tz * m;

    int px = ix & 1, py = iy & 1, pz = iz & 1;
    int pg = (px << 2) | (py << 1) | pz;
    // slots sx=ix+px etc. are even; quad coords:
    int xq = (ix + px) >> 1, yq = (iy + py) >> 1, zq = (iz + pz) >> 1;
    int idx = (((xq * 32 + yq) * 32 + zq) << 3);   // aligned 8-half block

    __half* addr = g_oct[pg] + (((size_t)b << 18) + idx);

    unsigned h0 = pack2(wx0 * wy0 * wz0, wx0 * wy0 * wz1);  // (x ,y ,z /z+1)
    unsigned h1 = pack2(wx0 * wy1 * wz0, wx0 * wy1 * wz1);  // (x ,y+1, .. )
    unsigned h2 = pack2(wx1 * wy0 * wz0, wx1 * wy0 * wz1);  // (x+1,y , .. )
    unsigned h3 = pack2(wx1 * wy1 * wz0, wx1 * wy1 * wz1);  // (x+1,y+1,.. )
    red_v4h2(addr, h0, h1, h2, h3);
}

__global__ void merge_oct_kernel(float* __restrict__ out, int total) {
    int i = blockIdx.x * blockDim.x + threadIdx.x;
    if (i >= total) return;
    int b = i >> 18;
    int r = i & (GRID3 - 1);
    int x = r >> 12, y = (r >> 6) & 63, z = r & 63;

    float s = 0.0f;
    #pragma unroll
    for (int pg = 0; pg < 8; pg++) {
        int px = pg >> 2, py = (pg >> 1) & 1, pz = pg & 1;
        int sx = x + px, sy = y + py, sz = z + pz;
        if (sx < GSIDE && sy < GSIDE && sz < GSIDE) {
            int idx = ((((sx >> 1) * 32 + (sy >> 1)) * 32 + (sz >> 1)) << 3)
                      | ((sx & 1) << 2) | ((sy & 1) << 1) | (sz & 1);
            s += __half2float(g_oct[pg][((size_t)b << 18) + idx]);
        }
    }
    out[i] = s;
}

// ---- fp32 fallback (round-1 design) for unexpected shapes ----
__global__ void scatter_f32_kernel(const float* __restrict__ pt,
                                   float* __restrict__ out, int N) {
    int n = blockIdx.x * blockDim.x + threadIdx.x;
    int b = blockIdx.y;
    if (n >= N) return;
    const float* p = pt + ((size_t)b * N + n) * 3;
    float x = p[0] * 32.f, y = p[1] * 32.f, z = p[2] * 32.f;
    float m = ((x + y + z) != 0.0f) ? 1.0f : 0.0f;
    float fx = floorf(x), fy = floorf(y), fz = floorf(z);
    float tx = x - fx, ty = y - fy, tz = z - fz;
    int ix = min(max((int)fx + 32, 0), 62);
    int iy = min(max((int)fy + 32, 0), 62);
    int iz = min(max((int)fz + 32, 0), 62);
    float wx0 = 1.f - tx, wy0 = 1.f - ty;
    float wz0 = (1.f - tz) * m, wz1 = tz * m;
    float* g = out + (size_t)b * GRID3;
    float* r = g + (((size_t)ix * GSIDE + iy) * GSIDE + iz);
    red_f32(r,                       wx0 * wy0 * wz0);
    red_f32(r + 1,                   wx0 * wy0 * wz1);
    red_f32(r + GSIDE,               wx0 * ty  * wz0);
    red_f32(r + GSIDE + 1,           wx0 * ty  * wz1);
    red_f32(r + GSIDE * GSIDE,             tx * wy0 * wz0);
    red_f32(r + GSIDE * GSIDE + 1,         tx * wy0 * wz1);
    red_f32(r + GSIDE * GSIDE + GSIDE,     tx * ty  * wz0);
    red_f32(r + GSIDE * GSIDE + GSIDE + 1, tx * ty  * wz1);
}

extern "C" void kernel_launch(void* const* d_in, const int* in_sizes, int n_in,
                              void* d_out, int out_size) {
    const float* pt  = (const float*)d_in[0];
    float*       out = (float*)d_out;

    int B = out_size / GRID3;
    if (B < 1) B = 1;
    int N = (in_sizes[0] / 3) / B;

    if (B <= CAP_B) {
        void* sp = nullptr;
        cudaGetSymbolAddress(&sp, g_oct);
        cudaMemsetAsync(sp, 0, sizeof(g_oct));

        dim3 block(256, 1, 1);
        dim3 grid((N + 255) / 256, B, 1);
        scatter_oct_kernel<<<grid, block>>>(pt, N);

        int total = B * GRID3;
        merge_oct_kernel<<<(total + 255) / 256, 256>>>(out, total);
    } else {
        cudaMemsetAsync(d_out, 0, (size_t)out_size * sizeof(float));
        dim3 block(256, 1, 1);
        dim3 grid((N + 255) / 256, B, 1);
        scatter_f32_kernel<<<grid, block>>>(pt, out, N);
    }
}

// round 13
// speedup vs baseline: 17.9071x; 1.5107x over previous
#include <cuda_runtime.h>
#include <cuda_fp16.h>
#include <cstdint>
#include <math.h>

// Trilinear scatter of B x N points into B x 64^3 grids.
// Scatter: all 8 corners of a point go into ONE red.global.add.noftz.v4.f16x2
// (octant layout: 8 parity grids, 8-half block = one 2x2x2 corner cube).
// Merge: one thread per output quad cell (2x2x2 voxels): 27 uint4 loads with
// compile-time extraction instead of 64 scalar u16 gathers.
#define HALF_EXT 32
#define GSIDE    64
#define GRID3    (GSIDE * GSIDE * GSIDE)     // 1<<18
#define CAP_B    32

// 8 parity grids x 32 batches x 64^3 f16 = 134 MB scratch.
__device__ __align__(16) __half g_oct[8][(size_t)CAP_B * GRID3];

__device__ __forceinline__ unsigned pack2(float lo, float hi) {
    __half2 v = __floats2half2_rn(lo, hi);
    return *(const unsigned*)&v;
}
__device__ __forceinline__ void red_v4h2(__half* p, unsigned a, unsigned b,
                                         unsigned c, unsigned d) {
    asm volatile("red.global.add.noftz.v4.f16x2 [%0], {%1,%2,%3,%4};"
                 :: "l"(p), "r"(a), "r"(b), "r"(c), "r"(d) : "memory");
}
__device__ __forceinline__ void red_f32(float* a, float v) {
    asm volatile("red.global.add.f32 [%0], %1;" :: "l"(a), "f"(v) : "memory");
}

__global__ void scatter_oct_kernel(const float* __restrict__ pt, int N) {
    int n = blockIdx.x * blockDim.x + threadIdx.x;
    int b = blockIdx.y;
    if (n >= N) return;

    const float* p = pt + ((size_t)b * N + n) * 3;
    float x = p[0] * (float)HALF_EXT;
    float y = p[1] * (float)HALF_EXT;
    float z = p[2] * (float)HALF_EXT;

    float m = ((x + y + z) != 0.0f) ? 1.0f : 0.0f;   // ref drops sum==0 points

    float fx = floorf(x), fy = floorf(y), fz = floorf(z);
    float tx = x - fx, ty = y - fy, tz = z - fz;

    int ix = min(max((int)fx + HALF_EXT, 0), GSIDE - 2);
    int iy = min(max((int)fy + HALF_EXT, 0), GSIDE - 2);
    int iz = min(max((int)fz + HALF_EXT, 0), GSIDE - 2);

    float wx0 = 1.0f - tx, wx1 = tx;
    float wy0 = 1.0f - ty, wy1 = ty;
    float wz0 = (1.0f - tz) * m, wz1 = tz * m;

    int px = ix & 1, py = iy & 1, pz = iz & 1;
    int pg = (px << 2) | (py << 1) | pz;
    int xq = (ix + px) >> 1, yq = (iy + py) >> 1, zq = (iz + pz) >> 1;
    int idx = (((xq * 32 + yq) * 32 + zq) << 3);     // aligned 8-half block

    __half* addr = g_oct[pg] + (((size_t)b << 18) + idx);

    unsigned h0 = pack2(wx0 * wy0 * wz0, wx0 * wy0 * wz1);
    unsigned h1 = pack2(wx0 * wy1 * wz0, wx0 * wy1 * wz1);
    unsigned h2 = pack2(wx1 * wy0 * wz0, wx1 * wy0 * wz1);
    unsigned h3 = pack2(wx1 * wy1 * wz0, wx1 * wy1 * wz1);
    red_v4h2(addr, h0, h1, h2, h3);
}

// One thread per output quad cell (2x2x2 voxels). For parity grid p the
// needed slots live in blocks at quad offsets {0..px}x{0..py}x{0..pz}:
// 27 vector loads total, all extraction indices compile-time.
__global__ void merge_quad_kernel(float* __restrict__ out, int nThreads) {
    int t = blockIdx.x * blockDim.x + threadIdx.x;
    if (t >= nThreads) return;
    int b  = t >> 15;                 // 32768 quads per batch
    int q  = t & 32767;
    int xq = q >> 10, yq = (q >> 5) & 31, zq = q & 31;

    float2 acc[2][2];
    acc[0][0] = make_float2(0.f, 0.f); acc[0][1] = make_float2(0.f, 0.f);
    acc[1][0] = make_float2(0.f, 0.f); acc[1][1] = make_float2(0.f, 0.f);
    const size_t bofs = (size_t)b << 18;

    #pragma unroll
    for (int pg = 0; pg < 8; pg++) {
        const int px = pg >> 2, py = (pg >> 1) & 1, pz = pg & 1;
        unsigned w[2][2][2][4];
        #pragma unroll
        for (int a = 0; a <= px; a++)
            #pragma unroll
            for (int e = 0; e <= py; e++)
                #pragma unroll
                for (int c = 0; c <= pz; c++) {
                    int qx = xq + a, qy = yq + e, qz = zq + c;
                    uint4 v = make_uint4(0u, 0u, 0u, 0u);
                    if (qx < 32 && qy < 32 && qz < 32)
                        v = *(const uint4*)(g_oct[pg] + bofs +
                              (size_t)(((((qx << 5) | qy) << 5) | qz) << 3));
                    w[a][e][c][0] = v.x; w[a][e][c][1] = v.y;
                    w[a][e][c][2] = v.z; w[a][e][c][3] = v.w;
                }
        #pragma unroll
        for (int xl = 0; xl < 2; xl++)
            #pragma unroll
            for (int yl = 0; yl < 2; yl++) {
                const int a  = (xl + px) >> 1;
                const int e  = (yl + py) >> 1;
                const int wi = (((xl + px) & 1) << 1) | ((yl + py) & 1);
                unsigned word;
                if (pz == 0) {
                    word = w[a][e][0][wi];                 // halves = (z, z+1)
                } else {
                    // voxel z at high half of c=0 word, voxel z+1 at low of c=1
                    word = (w[a][e][0][wi] >> 16) | (w[a][e][1][wi] << 16);
                }
                float2 f = __half22float2(*(const __half2*)&word);
                acc[xl][yl].x += f.x;
                acc[xl][yl].y += f.y;
            }
    }

    float* o = out + bofs + ((size_t)(xq << 1) << 12) + ((yq << 1) << 6) + (zq << 1);
    *(float2*)(o)               = acc[0][0];
    *(float2*)(o + 64)          = acc[0][1];
    *(float2*)(o + 4096)        = acc[1][0];
    *(float2*)(o + 4096 + 64)   = acc[1][1];
}

// ---- fp32 fallback (round-1 design) for unexpected shapes ----
__global__ void scatter_f32_kernel(const float* __restrict__ pt,
                                   float* __restrict__ out, int N) {
    int n = blockIdx.x * blockDim.x + threadIdx.x;
    int b = blockIdx.y;
    if (n >= N) return;
    const float* p = pt + ((size_t)b * N + n) * 3;
    float x = p[0] * 32.f, y = p[1] * 32.f, z = p[2] * 32.f;
    float m = ((x + y + z) != 0.0f) ? 1.0f : 0.0f;
    float fx = floorf(x), fy = floorf(y), fz = floorf(z);
    float tx = x - fx, ty = y - fy, tz = z - fz;
    int ix = min(max((int)fx + 32, 0), 62);
    int iy = min(max((int)fy + 32, 0), 62);
    int iz = min(max((int)fz + 32, 0), 62);
    float wx0 = 1.f - tx, wy0 = 1.f - ty;
    float wz0 = (1.f - tz) * m, wz1 = tz * m;
    float* g = out + (size_t)b * GRID3;
    float* r = g + (((size_t)ix * GSIDE + iy) * GSIDE + iz);
    red_f32(r,                       wx0 * wy0 * wz0);
    red_f32(r + 1,                   wx0 * wy0 * wz1);
    red_f32(r + GSIDE,               wx0 * ty  * wz0);
    red_f32(r + GSIDE + 1,           wx0 * ty  * wz1);
    red_f32(r + GSIDE * GSIDE,             tx * wy0 * wz0);
    red_f32(r + GSIDE * GSIDE + 1,         tx * wy0 * wz1);
    red_f32(r + GSIDE * GSIDE + GSIDE,     tx * ty  * wz0);
    red_f32(r + GSIDE * GSIDE + GSIDE + 1, tx * ty  * wz1);
}

extern "C" void kernel_launch(void* const* d_in, const int* in_sizes, int n_in,
                              void* d_out, int out_size) {
    const float* pt  = (const float*)d_in[0];
    float*       out = (float*)d_out;

    int B = out_size / GRID3;
    if (B < 1) B = 1;
    int N = (in_sizes[0] / 3) / B;

    if (B <= CAP_B) {
        void* sp = nullptr;
        cudaGetSymbolAddress(&sp, g_oct);
        cudaMemsetAsync(sp, 0, sizeof(g_oct));

        dim3 block(256, 1, 1);
        dim3 grid((N + 255) / 256, B, 1);
        scatter_oct_kernel<<<grid, block>>>(pt, N);

        int nThreads = B * 32768;
        merge_quad_kernel<<<(nThreads + 255) / 256, 256>>>(out, nThreads);
    } else {
        cudaMemsetAsync(d_out, 0, (size_t)out_size * sizeof(float));
        dim3 block(256, 1, 1);
        dim3 grid((N + 255) / 256, B, 1);
        scatter_f32_kernel<<<grid, block>>>(pt, out, N);
    }
}